// round 16
// baseline (speedup 1.0000x reference)
#include <cuda_runtime.h>
#include <cstdint>

// Problem: x[2,200000,32] f32, pos[2,200000,3] f32, kernel[3,3,3,32,32] f32,
// bias[32] f32 -> out[2,32,66,66,66] f32.
#define NPART 400000
#define NPERB 200000
#define DD    66
#define HWP   4356
#define DHW   287496
#define NCELL 524288        // 2 * 64^3 cells (full 3D cell sort)

// Channel-last scratch [2*DHW][32]; zero at module load, re-zeroed at end of
// every launch by the standalone zero kernel (proven configuration).
__device__ float g_scratch[(size_t)2 * DHW * 32];          // 73.6 MB

// Sort state. g_hist zero at load; re-zeroed by the tail zero kernel.
__device__ int g_hist[NCELL];        // hist -> scanned offsets -> cursors
__device__ int g_bsum[512];
__device__ int g_cell[NPART];
__device__ int g_sorted[NPART];

// B operands in MMA *fragment order*: [tap][nb][lane] -> uint4 = 4 packed
// bf16x2 regs (m=0..3). Thread (gid,tig) reg m = B[n=nb*8+gid][k=8m+2tig,+1].
__device__ __align__(16) uint4 g_BfH[27][4][32];
__device__ __align__(16) uint4 g_BfL[27][4][32];

// ---------------- helpers --------------------------------------------------
__device__ __forceinline__ unsigned short f2bf(float f) {
    unsigned short u; asm("cvt.rn.bf16.f32 %0, %1;" : "=h"(u) : "f"(f)); return u;
}
__device__ __forceinline__ float bf2f(unsigned short u) {
    return __uint_as_float(((uint32_t)u) << 16);
}
__device__ __forceinline__ uint32_t smem_u32(const void* p) {
    uint32_t a;
    asm("{ .reg .u64 t; cvta.to.shared.u64 t, %1; cvt.u32.u64 %0, t; }"
        : "=r"(a) : "l"(p));
    return a;
}
__device__ __forceinline__ void ldm4(uint32_t* r, uint32_t addr) {
    asm volatile("ldmatrix.sync.aligned.m8n8.x4.shared.b16 {%0,%1,%2,%3}, [%4];"
                 : "=r"(r[0]), "=r"(r[1]), "=r"(r[2]), "=r"(r[3]) : "r"(addr));
}
__device__ __forceinline__ void mma_bf16(float* d, const uint32_t* a,
                                         uint32_t b0, uint32_t b1) {
    asm volatile(
        "mma.sync.aligned.m16n8k16.row.col.f32.bf16.bf16.f32 "
        "{%0,%1,%2,%3}, {%4,%5,%6,%7}, {%8,%9}, {%0,%1,%2,%3};"
        : "+f"(d[0]), "+f"(d[1]), "+f"(d[2]), "+f"(d[3])
        : "r"(a[0]), "r"(a[1]), "r"(a[2]), "r"(a[3]), "r"(b0), "r"(b1));
}

// ---------------------------------------------------------------------------
// Sort pass 1: per-particle cell id + histogram.
// ---------------------------------------------------------------------------
__global__ void prep_kernel(const float* __restrict__ pos) {
    const int pid = blockIdx.x * blockDim.x + threadIdx.x;
    if (pid >= NPART) return;
    const int bx = (int)(pos[pid * 3 + 0] * 64.f);
    const int by = (int)(pos[pid * 3 + 1] * 64.f);
    const int bz = (int)(pos[pid * 3 + 2] * 64.f);
    const int b  = (pid >= NPERB) ? 1 : 0;
    const int cell = ((b * 64 + bx) * 64 + by) * 64 + bz;
    g_cell[pid] = cell;
    atomicAdd(&g_hist[cell], 1);
}

// ---------------------------------------------------------------------------
// Sort pass 2a: block-local exclusive scan (512 blocks x 1024 threads).
// g_hist[i] := exclusive-within-block; g_bsum[blk] := block total.
// ---------------------------------------------------------------------------
__global__ void scanA_kernel() {
    __shared__ int wsum[32];
    const int tid = threadIdx.x;
    const int i   = blockIdx.x * 1024 + tid;
    const int lane = tid & 31, wi = tid >> 5;
    const int v = g_hist[i];
    int s = v;
#pragma unroll
    for (int d = 1; d < 32; d <<= 1) {
        const int n = __shfl_up_sync(0xffffffffu, s, d);
        if (lane >= d) s += n;
    }
    if (lane == 31) wsum[wi] = s;
    __syncthreads();
    if (wi == 0) {
        int wv = wsum[lane];
#pragma unroll
        for (int d = 1; d < 32; d <<= 1) {
            const int n = __shfl_up_sync(0xffffffffu, wv, d);
            if (lane >= d) wv += n;
        }
        wsum[lane] = wv;
    }
    __syncthreads();
    const int wexcl = (wi == 0) ? 0 : wsum[wi - 1];
    g_hist[i] = wexcl + s - v;
    if (tid == 1023) g_bsum[blockIdx.x] = wexcl + s;
}

// ---------------------------------------------------------------------------
// Sort pass 2b: exclusive scan of the 512 block sums (1 block x 512 threads).
// ---------------------------------------------------------------------------
__global__ void scanB_kernel() {
    __shared__ int wsum[16];
    const int tid = threadIdx.x;
    const int lane = tid & 31, wi = tid >> 5;   // 16 warps
    const int v = g_bsum[tid];
    int s = v;
#pragma unroll
    for (int d = 1; d < 32; d <<= 1) {
        const int n = __shfl_up_sync(0xffffffffu, s, d);
        if (lane >= d) s += n;
    }
    if (lane == 31) wsum[wi] = s;
    __syncthreads();
    if (wi == 0 && lane < 16) {
        int wv = wsum[lane];
#pragma unroll
        for (int d = 1; d < 16; d <<= 1) {
            const int n = __shfl_up_sync(0x0000ffffu, wv, d);
            if (lane >= d) wv += n;
        }
        wsum[lane] = wv;
    }
    __syncthreads();
    const int wexcl = (wi == 0) ? 0 : wsum[wi - 1];
    g_bsum[tid] = wexcl + s - v;
}

// ---------------------------------------------------------------------------
// Sort pass 2c: g_hist[i] += block offset  (global exclusive offsets/cursors).
// ---------------------------------------------------------------------------
__global__ void scanC_kernel() {
    const int i = blockIdx.x * 1024 + threadIdx.x;
    g_hist[i] += g_bsum[i >> 10];
}

// ---------------------------------------------------------------------------
// Sort pass 3: scatter pids into cell-sorted order (atomic cursors in g_hist).
// ---------------------------------------------------------------------------
__global__ void scatter_kernel() {
    const int pid = blockIdx.x * blockDim.x + threadIdx.x;
    if (pid >= NPART) return;
    const int p = atomicAdd(&g_hist[g_cell[pid]], 1);
    g_sorted[p] = pid;
}

// ---------------------------------------------------------------------------
// Prebuild: hi/lo bf16 split of kernel, written directly in fragment order.
// ---------------------------------------------------------------------------
__global__ void prebuild_kernel(const float* __restrict__ kern) {
    const int t    = blockIdx.x;          // tap 0..26
    const int nb   = threadIdx.x >> 5;
    const int lane = threadIdx.x & 31;
    const int gid  = lane >> 2, tig = lane & 3;
    const int n    = nb * 8 + gid;        // co
    uint32_t rh[4], rl[4];
#pragma unroll
    for (int m = 0; m < 4; ++m) {
        const int k0 = 8 * m + 2 * tig;   // ci
        const float f0 = kern[(size_t)t * 1024 + k0 * 32 + n];
        const float f1 = kern[(size_t)t * 1024 + (k0 + 1) * 32 + n];
        const unsigned short h0 = f2bf(f0), h1 = f2bf(f1);
        const unsigned short l0 = f2bf(f0 - bf2f(h0)), l1 = f2bf(f1 - bf2f(h1));
        rh[m] = (uint32_t)h0 | ((uint32_t)h1 << 16);
        rl[m] = (uint32_t)l0 | ((uint32_t)l1 << 16);
    }
    g_BfH[t][nb][lane] = make_uint4(rh[0], rh[1], rh[2], rh[3]);
    g_BfL[t][nb][lane] = make_uint4(rl[0], rl[1], rl[2], rl[3]);
}

// ---------------------------------------------------------------------------
// Main kernel (R15 + cell-sorted tiles + warp merge): CTA = 4 independent
// warps, warp = 32 CELL-SORTED particles. __match_any_sync on node base gives
// equal-cell lane sets; only the leader lane REDs, after summing the set's pb
// rows (LDS) — cutting L2-atomic lane-ops by the duplicate fraction.
// ---------------------------------------------------------------------------
#define OFF_AH 0
#define OFF_AL 10240
#define OFF_WX 20480
#define OFF_WY 22016
#define OFF_WZ 23552
#define OFF_NB 25088
#define OFF_MK 25600
#define OFF_PB 26112
#define SMEM_BYTES (OFF_PB + 4 * 2 * 1152 * 4)   // 62976

__global__ __launch_bounds__(128) void main_kernel(
    const float* __restrict__ x,
    const float* __restrict__ pos,
    const float* __restrict__ bias)
{
    extern __shared__ __align__(16) char smem[];
    const int tid  = threadIdx.x;
    const int w    = tid >> 5;
    const int lane = tid & 31;
    const int gid  = lane >> 2;          // fragment row id
    const int tig  = lane & 3;           // thread-in-group (col pair)
    const int pid  = g_sorted[blockIdx.x * 128 + w * 32 + lane];
    const uint32_t sb = smem_u32(smem);

    // ---- stage A: x -> bf16 hi/lo rows (80B stride, conflict-free) ----
    {
        float xv[32];
        const float4* xp = reinterpret_cast<const float4*>(x + (size_t)pid * 32);
#pragma unroll
        for (int t = 0; t < 8; ++t) {
            const float4 v = xp[t];
            xv[4 * t] = v.x; xv[4 * t + 1] = v.y; xv[4 * t + 2] = v.z; xv[4 * t + 3] = v.w;
        }
        uint32_t hw[16], lw[16];
#pragma unroll
        for (int k = 0; k < 16; ++k) {
            const float f0 = xv[2 * k], f1 = xv[2 * k + 1];
            const unsigned short h0 = f2bf(f0), h1 = f2bf(f1);
            const unsigned short l0 = f2bf(f0 - bf2f(h0)), l1 = f2bf(f1 - bf2f(h1));
            hw[k] = (uint32_t)h0 | ((uint32_t)h1 << 16);
            lw[k] = (uint32_t)l0 | ((uint32_t)l1 << 16);
        }
        char* rH = smem + OFF_AH + (w * 32 + lane) * 80;
        char* rL = smem + OFF_AL + (w * 32 + lane) * 80;
#pragma unroll
        for (int c = 0; c < 4; ++c) {
            reinterpret_cast<uint4*>(rH)[c] = make_uint4(hw[4*c], hw[4*c+1], hw[4*c+2], hw[4*c+3]);
            reinterpret_cast<uint4*>(rL)[c] = make_uint4(lw[4*c], lw[4*c+1], lw[4*c+2], lw[4*c+3]);
        }
    }

    // ---- weights + node + equal-node mask for own particle ----
    {
        const float px = pos[pid * 3 + 0] * 64.f;
        const float py = pos[pid * 3 + 1] * 64.f;
        const float pz = pos[pid * 3 + 2] * 64.f;
        const int bx = (int)px, by = (int)py, bz = (int)pz;
        const float fx = px - (float)bx - 0.5f;
        const float fy = py - (float)by - 0.5f;
        const float fz = pz - (float)bz - 0.5f;
        float* WX = reinterpret_cast<float*>(smem + OFF_WX) + w * 96;
        float* WY = reinterpret_cast<float*>(smem + OFF_WY) + w * 96;
        float* WZ = reinterpret_cast<float*>(smem + OFF_WZ) + w * 96;
        WX[lane]      = 0.5f * (0.5f - fx) * (0.5f - fx);
        WX[32 + lane] = 0.75f - fx * fx;
        WX[64 + lane] = 0.5f * (0.5f + fx) * (0.5f + fx);
        WY[lane]      = 0.5f * (0.5f - fy) * (0.5f - fy);
        WY[32 + lane] = 0.75f - fy * fy;
        WY[64 + lane] = 0.5f * (0.5f + fy) * (0.5f + fy);
        WZ[lane]      = 0.5f * (0.5f - fz) * (0.5f - fz);
        WZ[32 + lane] = 0.75f - fz * fz;
        WZ[64 + lane] = 0.5f * (0.5f + fz) * (0.5f + fz);
        const int b = (pid >= NPERB) ? 1 : 0;
        const int ndv = b * DHW + bx * HWP + by * DD + bz;
        reinterpret_cast<int*>(smem + OFF_NB)[w * 32 + lane] = ndv;
        // Lanes with identical node base (same cell) -> merge set.
        const unsigned mk = __match_any_sync(0xffffffffu, ndv);
        reinterpret_cast<unsigned*>(smem + OFF_MK)[w * 32 + lane] = mk;
    }
    __syncwarp();    // all staged data is per-warp; warps stay independent

    // ---- per-lane constants ----
    float bias_r[4][2];
#pragma unroll
    for (int nb = 0; nb < 4; ++nb) {
        bias_r[nb][0] = bias[nb * 8 + 2 * tig];
        bias_r[nb][1] = bias[nb * 8 + 2 * tig + 1];
    }

    // ---- A fragments (persistent registers) ----
    uint32_t aH[2][2][4], aL[2][2][4];
#pragma unroll
    for (int mb = 0; mb < 2; ++mb)
#pragma unroll
        for (int ks = 0; ks < 2; ++ks) {
            const uint32_t off = (uint32_t)((w * 32 + mb * 16 + (lane & 15)) * 80
                                            + ks * 32 + (lane >> 4) * 16);
            ldm4(aH[mb][ks], sb + OFF_AH + off);
            ldm4(aL[mb][ks], sb + OFF_AL + off);
        }

    const float* WX  = reinterpret_cast<float*>(smem + OFF_WX) + w * 96;
    const float* WY  = reinterpret_cast<float*>(smem + OFF_WY) + w * 96;
    const float* WZ  = reinterpret_cast<float*>(smem + OFF_WZ) + w * 96;
    const int*   NBw = reinterpret_cast<int*>(smem + OFF_NB) + w * 32;
    const unsigned* MKw = reinterpret_cast<unsigned*>(smem + OFF_MK) + w * 32;
    float* const pb0 = reinterpret_cast<float*>(smem + OFF_PB) + w * 2304; // 2x1152

    // ---- RED slot constants: this thread's 8 p-slots (p = lane>>3 + 4i) ----
    int nb8[8];
    unsigned mk8[8];
    int lead8[8];
#pragma unroll
    for (int i = 0; i < 8; ++i) {
        const int p = (lane >> 3) + 4 * i;
        nb8[i]  = NBw[p];
        mk8[i]  = MKw[p];
        lead8[i] = ((mk8[i] & ((1u << p) - 1u)) == 0u);   // p is lowest set bit
    }

    for (int g = 0; g < 9; ++g) {
        const int oi = g / 3, oj = g % 3;

        float w12[4];
#pragma unroll
        for (int i = 0; i < 4; ++i) {
            const int p = gid + i * 8;
            w12[i] = WX[oi * 32 + p] * WY[oj * 32 + p];
        }

        for (int ok = 0; ok < 3; ++ok) {
            // ---- B fragments: direct coalesced LDG.128 (fragment order) ----
            const int tap = g * 3 + ok;
            uint4 bhv[4], blv[4];
#pragma unroll
            for (int nb = 0; nb < 4; ++nb) {
                bhv[nb] = g_BfH[tap][nb][lane];
                blv[nb] = g_BfL[tap][nb][lane];
            }
            const uint32_t* bh = reinterpret_cast<const uint32_t*>(bhv);
            const uint32_t* bl = reinterpret_cast<const uint32_t*>(blv);

            // ---- 3-term split MMA ----
            float d[2][4][4];
#pragma unroll
            for (int mb = 0; mb < 2; ++mb)
#pragma unroll
                for (int nb = 0; nb < 4; ++nb) {
#pragma unroll
                    for (int q = 0; q < 4; ++q) d[mb][nb][q] = 0.f;
                    mma_bf16(d[mb][nb], aH[mb][0], bh[nb * 4 + 0], bh[nb * 4 + 1]);
                    mma_bf16(d[mb][nb], aH[mb][1], bh[nb * 4 + 2], bh[nb * 4 + 3]);
                    mma_bf16(d[mb][nb], aH[mb][0], bl[nb * 4 + 0], bl[nb * 4 + 1]);
                    mma_bf16(d[mb][nb], aH[mb][1], bl[nb * 4 + 2], bl[nb * 4 + 3]);
                    mma_bf16(d[mb][nb], aL[mb][0], bh[nb * 4 + 0], bh[nb * 4 + 1]);
                    mma_bf16(d[mb][nb], aL[mb][1], bh[nb * 4 + 2], bh[nb * 4 + 3]);
                }

            float w3[4];
#pragma unroll
            for (int i = 0; i < 4; ++i)
                w3[i] = w12[i] * WZ[ok * 32 + gid + i * 8];

            // ---- weighted fragments -> pb [p][co], parity double-buffered ----
            float* const pbw = pb0 + ((g * 3 + ok) & 1) * 1152;
#pragma unroll
            for (int mb = 0; mb < 2; ++mb)
#pragma unroll
                for (int nb = 0; nb < 4; ++nb) {
                    const int r0 = mb * 16 + gid;
                    const int c  = nb * 8 + 2 * tig;
                    float2 v0, v1;
                    v0.x = (d[mb][nb][0] + bias_r[nb][0]) * w3[mb * 2];
                    v0.y = (d[mb][nb][1] + bias_r[nb][1]) * w3[mb * 2];
                    v1.x = (d[mb][nb][2] + bias_r[nb][0]) * w3[mb * 2 + 1];
                    v1.y = (d[mb][nb][3] + bias_r[nb][1]) * w3[mb * 2 + 1];
                    *reinterpret_cast<float2*>(&pbw[r0 * 36 + c])       = v0;
                    *reinterpret_cast<float2*>(&pbw[(r0 + 8) * 36 + c]) = v1;
                }
            __syncwarp();

            // ---- merged float4 REDs: leader lane sums its equal-cell set ----
            const int obase = oi * HWP + oj * DD + ok;
            const int q4 = (lane & 7) * 4;
#pragma unroll
            for (int i = 0; i < 8; ++i) {
                if (lead8[i]) {
                    float4 v = make_float4(0.f, 0.f, 0.f, 0.f);
                    unsigned m = mk8[i];
                    do {
                        const int j = __ffs(m) - 1;
                        m &= m - 1;
                        const float4 t =
                            *reinterpret_cast<const float4*>(&pbw[j * 36 + q4]);
                        v.x += t.x; v.y += t.y; v.z += t.z; v.w += t.w;
                    } while (m);
                    atomicAdd(reinterpret_cast<float4*>(
                                  g_scratch + (size_t)(nb8[i] + obase) * 32 + q4), v);
                }
            }
            // no trailing syncwarp (parity double-buffer).
        }
    }
}

// ---------------------------------------------------------------------------
// Transpose scratch [b][node][c] -> out [b][c][node]  (read-only on scratch).
// ---------------------------------------------------------------------------
__global__ void transpose_kernel(float* __restrict__ out) {
    __shared__ float t[32][33];
    const int tid = threadIdx.x;          // 256
    const int b   = blockIdx.y;
    const int nd0 = blockIdx.x * 32;

    {
        const int ty = tid >> 3, tx = tid & 7;
        const int nd = nd0 + ty;
        if (nd < DHW) {
            const float4 v = *reinterpret_cast<const float4*>(
                &g_scratch[((size_t)b * DHW + nd) * 32 + 4 * tx]);
            t[ty][4 * tx + 0] = v.x;
            t[ty][4 * tx + 1] = v.y;
            t[ty][4 * tx + 2] = v.z;
            t[ty][4 * tx + 3] = v.w;
        }
    }
    __syncthreads();

    const int c0 = tid >> 5, n = tid & 31;
    const int nd = nd0 + n;
    if (nd < DHW) {
#pragma unroll
        for (int k = 0; k < 4; ++k) {
            const int c = c0 + 8 * k;
            out[((size_t)b * 32 + c) * DHW + nd] = t[n][c];
        }
    }
}

// ---------------------------------------------------------------------------
// Tail: zero scratch + histogram for the next call.
// ---------------------------------------------------------------------------
__global__ void zero_scratch_kernel() {
    const size_t n4 = (size_t)2 * DHW * 32 / 4;
    float4* p = reinterpret_cast<float4*>(g_scratch);
    for (size_t i = (size_t)blockIdx.x * blockDim.x + threadIdx.x;
         i < n4; i += (size_t)gridDim.x * blockDim.x)
        p[i] = make_float4(0.f, 0.f, 0.f, 0.f);
    for (int i = blockIdx.x * blockDim.x + threadIdx.x;
         i < NCELL; i += gridDim.x * blockDim.x)
        g_hist[i] = 0;
}

// ---------------------------------------------------------------------------
extern "C" void kernel_launch(void* const* d_in, const int* in_sizes, int n_in,
                              void* d_out, int out_size)
{
    const float* x    = reinterpret_cast<const float*>(d_in[0]);
    const float* pos  = reinterpret_cast<const float*>(d_in[1]);
    const float* kern = reinterpret_cast<const float*>(d_in[2]);
    const float* bias = reinterpret_cast<const float*>(d_in[3]);
    float* out = reinterpret_cast<float*>(d_out);

    static int attr_done = 0;
    if (!attr_done) {
        cudaFuncSetAttribute(main_kernel,
                             cudaFuncAttributeMaxDynamicSharedMemorySize,
                             SMEM_BYTES);
        attr_done = 1;
    }

    prep_kernel<<<(NPART + 255) / 256, 256>>>(pos);
    scanA_kernel<<<512, 1024>>>();
    scanB_kernel<<<1, 512>>>();
    scanC_kernel<<<512, 1024>>>();
    scatter_kernel<<<(NPART + 255) / 256, 256>>>();
    prebuild_kernel<<<27, 128>>>(kern);
    main_kernel<<<NPART / 128, 128, SMEM_BYTES>>>(x, pos, bias);
    transpose_kernel<<<dim3((DHW + 31) / 32, 2), 256>>>(out);
    zero_scratch_kernel<<<4096, 256>>>();
}

// round 17
// speedup vs baseline: 1.5884x; 1.5884x over previous
#include <cuda_runtime.h>
#include <cstdint>

// Problem: x[2,200000,32] f32, pos[2,200000,3] f32, kernel[3,3,3,32,32] f32,
// bias[32] f32 -> out[2,32,66,66,66] f32.
#define NPART 400000
#define NPERB 200000
#define DD    66
#define HWP   4356
#define DHW   287496

// Channel-last scratch [2*DHW][32]; zero at module load, re-zeroed at end of
// every launch by the standalone zero kernel (proven configuration).
__device__ float g_scratch[(size_t)2 * DHW * 32];          // 73.6 MB

// B operands in MMA *fragment order*: [tap][nb][lane] -> uint4 = 4 packed
// bf16x2 regs (m=0..3). Thread (gid,tig) reg m = B[n=nb*8+gid][k=8m+2tig,+1].
__device__ __align__(16) uint4 g_BfH[27][4][32];
__device__ __align__(16) uint4 g_BfL[27][4][32];

// ---------------- helpers --------------------------------------------------
__device__ __forceinline__ unsigned short f2bf(float f) {
    unsigned short u; asm("cvt.rn.bf16.f32 %0, %1;" : "=h"(u) : "f"(f)); return u;
}
__device__ __forceinline__ float bf2f(unsigned short u) {
    return __uint_as_float(((uint32_t)u) << 16);
}
__device__ __forceinline__ uint32_t smem_u32(const void* p) {
    uint32_t a;
    asm("{ .reg .u64 t; cvta.to.shared.u64 t, %1; cvt.u32.u64 %0, t; }"
        : "=r"(a) : "l"(p));
    return a;
}
__device__ __forceinline__ void ldm4(uint32_t* r, uint32_t addr) {
    asm volatile("ldmatrix.sync.aligned.m8n8.x4.shared.b16 {%0,%1,%2,%3}, [%4];"
                 : "=r"(r[0]), "=r"(r[1]), "=r"(r[2]), "=r"(r[3]) : "r"(addr));
}
__device__ __forceinline__ void mma_bf16(float* d, const uint32_t* a,
                                         uint32_t b0, uint32_t b1) {
    asm volatile(
        "mma.sync.aligned.m16n8k16.row.col.f32.bf16.bf16.f32 "
        "{%0,%1,%2,%3}, {%4,%5,%6,%7}, {%8,%9}, {%0,%1,%2,%3};"
        : "+f"(d[0]), "+f"(d[1]), "+f"(d[2]), "+f"(d[3])
        : "r"(a[0]), "r"(a[1]), "r"(a[2]), "r"(a[3]), "r"(b0), "r"(b1));
}

// ---------------------------------------------------------------------------
// Prebuild: hi/lo bf16 split of kernel, written directly in fragment order.
// ---------------------------------------------------------------------------
__global__ void prebuild_kernel(const float* __restrict__ kern) {
    const int t    = blockIdx.x;          // tap 0..26
    const int nb   = threadIdx.x >> 5;
    const int lane = threadIdx.x & 31;
    const int gid  = lane >> 2, tig = lane & 3;
    const int n    = nb * 8 + gid;        // co
    uint32_t rh[4], rl[4];
#pragma unroll
    for (int m = 0; m < 4; ++m) {
        const int k0 = 8 * m + 2 * tig;   // ci
        const float f0 = kern[(size_t)t * 1024 + k0 * 32 + n];
        const float f1 = kern[(size_t)t * 1024 + (k0 + 1) * 32 + n];
        const unsigned short h0 = f2bf(f0), h1 = f2bf(f1);
        const unsigned short l0 = f2bf(f0 - bf2f(h0)), l1 = f2bf(f1 - bf2f(h1));
        rh[m] = (uint32_t)h0 | ((uint32_t)h1 << 16);
        rl[m] = (uint32_t)l0 | ((uint32_t)l1 << 16);
    }
    g_BfH[t][nb][lane] = make_uint4(rh[0], rh[1], rh[2], rh[3]);
    g_BfL[t][nb][lane] = make_uint4(rl[0], rl[1], rl[2], rl[3]);
}

// ---------------------------------------------------------------------------
// Main kernel: CTA = 4 independent warps, warp = 32 sequential particles.
// Per (oi,oj,ok): B fragments via coalesced LDG.128 (L1-resident), 3-term
// bf16-split MMA, staged epilogue (parity double-buffer, one syncwarp),
// 8 coalesced float4 REDs (4 particles x one FULL 128B line each).
// ---------------------------------------------------------------------------
#define OFF_AH 0
#define OFF_AL 10240
#define OFF_WX 20480
#define OFF_WY 22016
#define OFF_WZ 23552
#define OFF_NB 25088
#define OFF_PB 25600
#define SMEM_BYTES (OFF_PB + 4 * 2 * 1152 * 4)   // 62464

__global__ __launch_bounds__(128) void main_kernel(
    const float* __restrict__ x,
    const float* __restrict__ pos,
    const float* __restrict__ bias)
{
    extern __shared__ __align__(16) char smem[];
    const int tid  = threadIdx.x;
    const int w    = tid >> 5;
    const int lane = tid & 31;
    const int gid  = lane >> 2;          // fragment row id
    const int tig  = lane & 3;           // thread-in-group (col pair)
    const int pid  = blockIdx.x * 128 + w * 32 + lane;
    const uint32_t sb = smem_u32(smem);

    // ---- stage A: x -> bf16 hi/lo rows (80B stride, conflict-free) ----
    {
        float xv[32];
        const float4* xp = reinterpret_cast<const float4*>(x + (size_t)pid * 32);
#pragma unroll
        for (int t = 0; t < 8; ++t) {
            const float4 v = xp[t];
            xv[4 * t] = v.x; xv[4 * t + 1] = v.y; xv[4 * t + 2] = v.z; xv[4 * t + 3] = v.w;
        }
        uint32_t hw[16], lw[16];
#pragma unroll
        for (int k = 0; k < 16; ++k) {
            const float f0 = xv[2 * k], f1 = xv[2 * k + 1];
            const unsigned short h0 = f2bf(f0), h1 = f2bf(f1);
            const unsigned short l0 = f2bf(f0 - bf2f(h0)), l1 = f2bf(f1 - bf2f(h1));
            hw[k] = (uint32_t)h0 | ((uint32_t)h1 << 16);
            lw[k] = (uint32_t)l0 | ((uint32_t)l1 << 16);
        }
        char* rH = smem + OFF_AH + (w * 32 + lane) * 80;
        char* rL = smem + OFF_AL + (w * 32 + lane) * 80;
#pragma unroll
        for (int c = 0; c < 4; ++c) {
            reinterpret_cast<uint4*>(rH)[c] = make_uint4(hw[4*c], hw[4*c+1], hw[4*c+2], hw[4*c+3]);
            reinterpret_cast<uint4*>(rL)[c] = make_uint4(lw[4*c], lw[4*c+1], lw[4*c+2], lw[4*c+3]);
        }
    }

    // ---- weights + node for own particle ----
    {
        const float px = pos[pid * 3 + 0] * 64.f;
        const float py = pos[pid * 3 + 1] * 64.f;
        const float pz = pos[pid * 3 + 2] * 64.f;
        const int bx = (int)px, by = (int)py, bz = (int)pz;
        const float fx = px - (float)bx - 0.5f;
        const float fy = py - (float)by - 0.5f;
        const float fz = pz - (float)bz - 0.5f;
        float* WX = reinterpret_cast<float*>(smem + OFF_WX) + w * 96;
        float* WY = reinterpret_cast<float*>(smem + OFF_WY) + w * 96;
        float* WZ = reinterpret_cast<float*>(smem + OFF_WZ) + w * 96;
        WX[lane]      = 0.5f * (0.5f - fx) * (0.5f - fx);
        WX[32 + lane] = 0.75f - fx * fx;
        WX[64 + lane] = 0.5f * (0.5f + fx) * (0.5f + fx);
        WY[lane]      = 0.5f * (0.5f - fy) * (0.5f - fy);
        WY[32 + lane] = 0.75f - fy * fy;
        WY[64 + lane] = 0.5f * (0.5f + fy) * (0.5f + fy);
        WZ[lane]      = 0.5f * (0.5f - fz) * (0.5f - fz);
        WZ[32 + lane] = 0.75f - fz * fz;
        WZ[64 + lane] = 0.5f * (0.5f + fz) * (0.5f + fz);
        const int b = (pid >= NPERB) ? 1 : 0;
        reinterpret_cast<int*>(smem + OFF_NB)[w * 32 + lane] =
            b * DHW + bx * HWP + by * DD + bz;
    }
    __syncwarp();    // all staged data is per-warp; warps stay independent

    // ---- per-lane constants ----
    float bias_r[4][2];
#pragma unroll
    for (int nb = 0; nb < 4; ++nb) {
        bias_r[nb][0] = bias[nb * 8 + 2 * tig];
        bias_r[nb][1] = bias[nb * 8 + 2 * tig + 1];
    }

    // ---- A fragments (persistent registers) ----
    uint32_t aH[2][2][4], aL[2][2][4];
#pragma unroll
    for (int mb = 0; mb < 2; ++mb)
#pragma unroll
        for (int ks = 0; ks < 2; ++ks) {
            const uint32_t off = (uint32_t)((w * 32 + mb * 16 + (lane & 15)) * 80
                                            + ks * 32 + (lane >> 4) * 16);
            ldm4(aH[mb][ks], sb + OFF_AH + off);
            ldm4(aL[mb][ks], sb + OFF_AL + off);
        }

    const float* WX  = reinterpret_cast<float*>(smem + OFF_WX) + w * 96;
    const float* WY  = reinterpret_cast<float*>(smem + OFF_WY) + w * 96;
    const float* WZ  = reinterpret_cast<float*>(smem + OFF_WZ) + w * 96;
    const int*   NBw = reinterpret_cast<int*>(smem + OFF_NB) + w * 32;
    float* const pb0 = reinterpret_cast<float*>(smem + OFF_PB) + w * 2304; // 2x1152

    // ---- RED node bases: this thread's 8 p-slots are fixed (p=lane>>3 + 4i).
    int nb8[8];
#pragma unroll
    for (int i = 0; i < 8; ++i) nb8[i] = NBw[(lane >> 3) + 4 * i];

    for (int g = 0; g < 9; ++g) {
        const int oi = g / 3, oj = g % 3;

        float w12[4];
#pragma unroll
        for (int i = 0; i < 4; ++i) {
            const int p = gid + i * 8;
            w12[i] = WX[oi * 32 + p] * WY[oj * 32 + p];
        }

        for (int ok = 0; ok < 3; ++ok) {
            // ---- B fragments: direct coalesced LDG.128 (fragment order) ----
            const int tap = g * 3 + ok;
            uint4 bhv[4], blv[4];
#pragma unroll
            for (int nb = 0; nb < 4; ++nb) {
                bhv[nb] = g_BfH[tap][nb][lane];
                blv[nb] = g_BfL[tap][nb][lane];
            }
            const uint32_t* bh = reinterpret_cast<const uint32_t*>(bhv);
            const uint32_t* bl = reinterpret_cast<const uint32_t*>(blv);

            // ---- 3-term split MMA ----
            float d[2][4][4];
#pragma unroll
            for (int mb = 0; mb < 2; ++mb)
#pragma unroll
                for (int nb = 0; nb < 4; ++nb) {
#pragma unroll
                    for (int q = 0; q < 4; ++q) d[mb][nb][q] = 0.f;
                    mma_bf16(d[mb][nb], aH[mb][0], bh[nb * 4 + 0], bh[nb * 4 + 1]);
                    mma_bf16(d[mb][nb], aH[mb][1], bh[nb * 4 + 2], bh[nb * 4 + 3]);
                    mma_bf16(d[mb][nb], aH[mb][0], bl[nb * 4 + 0], bl[nb * 4 + 1]);
                    mma_bf16(d[mb][nb], aH[mb][1], bl[nb * 4 + 2], bl[nb * 4 + 3]);
                    mma_bf16(d[mb][nb], aL[mb][0], bh[nb * 4 + 0], bh[nb * 4 + 1]);
                    mma_bf16(d[mb][nb], aL[mb][1], bh[nb * 4 + 2], bh[nb * 4 + 3]);
                }

            float w3[4];
#pragma unroll
            for (int i = 0; i < 4; ++i)
                w3[i] = w12[i] * WZ[ok * 32 + gid + i * 8];

            // ---- weighted fragments -> pb [p][co], parity double-buffered ----
            float* const pbw = pb0 + ((g * 3 + ok) & 1) * 1152;
#pragma unroll
            for (int mb = 0; mb < 2; ++mb)
#pragma unroll
                for (int nb = 0; nb < 4; ++nb) {
                    const int r0 = mb * 16 + gid;
                    const int c  = nb * 8 + 2 * tig;
                    float2 v0, v1;
                    v0.x = (d[mb][nb][0] + bias_r[nb][0]) * w3[mb * 2];
                    v0.y = (d[mb][nb][1] + bias_r[nb][1]) * w3[mb * 2];
                    v1.x = (d[mb][nb][2] + bias_r[nb][0]) * w3[mb * 2 + 1];
                    v1.y = (d[mb][nb][3] + bias_r[nb][1]) * w3[mb * 2 + 1];
                    *reinterpret_cast<float2*>(&pbw[r0 * 36 + c])       = v0;
                    *reinterpret_cast<float2*>(&pbw[(r0 + 8) * 36 + c]) = v1;
                }
            __syncwarp();

            // ---- coalesced float4 REDs (4 particles x full 128B line each) ----
            const int obase = oi * HWP + oj * DD + ok;
#pragma unroll
            for (int i = 0; i < 8; ++i) {
                const int f = i * 32 + lane;
                const int p = f >> 3, q = f & 7;
                const int nd = nb8[i] + obase;            // register, no LDS
                const float4 v = *reinterpret_cast<const float4*>(&pbw[p * 36 + q * 4]);
                atomicAdd(reinterpret_cast<float4*>(
                              g_scratch + (size_t)nd * 32 + q * 4), v);
            }
            // no trailing syncwarp (parity double-buffer).
        }
    }
}

// ---------------------------------------------------------------------------
// Transpose scratch [b][node][c] -> out [b][c][node]  (read-only on scratch).
// One LDG.128 per thread, conflict-aware smem stage, coalesced row writes.
// ---------------------------------------------------------------------------
__global__ void transpose_kernel(float* __restrict__ out) {
    __shared__ float t[32][33];
    const int tid = threadIdx.x;          // 256
    const int b   = blockIdx.y;
    const int nd0 = blockIdx.x * 32;

    {
        const int ty = tid >> 3, tx = tid & 7;
        const int nd = nd0 + ty;
        if (nd < DHW) {
            const float4 v = *reinterpret_cast<const float4*>(
                &g_scratch[((size_t)b * DHW + nd) * 32 + 4 * tx]);
            t[ty][4 * tx + 0] = v.x;
            t[ty][4 * tx + 1] = v.y;
            t[ty][4 * tx + 2] = v.z;
            t[ty][4 * tx + 3] = v.w;
        }
    }
    __syncthreads();

    const int c0 = tid >> 5, n = tid & 31;
    const int nd = nd0 + n;
    if (nd < DHW) {
#pragma unroll
        for (int k = 0; k < 4; ++k) {
            const int c = c0 + 8 * k;
            out[((size_t)b * 32 + c) * DHW + nd] = t[n][c];
        }
    }
}

__global__ void zero_scratch_kernel() {
    const size_t n4 = (size_t)2 * DHW * 32 / 4;
    float4* p = reinterpret_cast<float4*>(g_scratch);
    for (size_t i = (size_t)blockIdx.x * blockDim.x + threadIdx.x;
         i < n4; i += (size_t)gridDim.x * blockDim.x)
        p[i] = make_float4(0.f, 0.f, 0.f, 0.f);
}

// ---------------------------------------------------------------------------
extern "C" void kernel_launch(void* const* d_in, const int* in_sizes, int n_in,
                              void* d_out, int out_size)
{
    const float* x    = reinterpret_cast<const float*>(d_in[0]);
    const float* pos  = reinterpret_cast<const float*>(d_in[1]);
    const float* kern = reinterpret_cast<const float*>(d_in[2]);
    const float* bias = reinterpret_cast<const float*>(d_in[3]);
    float* out = reinterpret_cast<float*>(d_out);

    static int attr_done = 0;
    if (!attr_done) {
        cudaFuncSetAttribute(main_kernel,
                             cudaFuncAttributeMaxDynamicSharedMemorySize,
                             SMEM_BYTES);
        attr_done = 1;
    }

    prebuild_kernel<<<27, 128>>>(kern);
    main_kernel<<<NPART / 128, 128, SMEM_BYTES>>>(x, pos, bias);
    transpose_kernel<<<dim3((DHW + 31) / 32, 2), 256>>>(out);
    zero_scratch_kernel<<<4096, 256>>>();
}